// round 17
// baseline (speedup 1.0000x reference)
#include <cuda_runtime.h>
#include <cuda_bf16.h>
#include <cuda_fp16.h>
#include <math.h>
#include <stdint.h>

// Problem constants
#define BDIM   8
#define HW     4096
#define CDIM   256
#define NHEAD  8
#define HC     32
#define MROWS  (BDIM * HW)   // 32768
#define QKVN   768
#define KV_CH  8

// ---------------------------------------------------------------------------
// Scratch (device globals)
// ---------------------------------------------------------------------------
__device__ __half  g_qkvh[(size_t)MROWS * QKVN];   // fp16 q,k,v
__device__ __half  g_xh[(size_t)MROWS * CDIM];     // fp16 x
__device__ __half  g_reth[(size_t)MROWS * CDIM];
__device__ __half  g_hidh[(size_t)MROWS * CDIM];
__device__ __half  g_wqh[(size_t)QKVN * CDIM];     // fp16 weights [N,K]
__device__ __half  g_w1h[CDIM * CDIM];
__device__ __half  g_w2h[CDIM * CDIM];
__device__ float   g_kvp[BDIM * NHEAD * KV_CH * HC * HC];

// ---------------------------------------------------------------------------
// PTX helpers
// ---------------------------------------------------------------------------
__device__ __forceinline__ uint32_t smem_u32(const void* p) {
    uint32_t a;
    asm("{ .reg .u64 t; cvta.to.shared.u64 t, %1; cvt.u32.u64 %0, t; }"
        : "=r"(a) : "l"(p));
    return a;
}

__device__ __forceinline__ void cp_async16(uint32_t dst, const void* src) {
    asm volatile("cp.async.cg.shared.global [%0], [%1], 16;"
                 :: "r"(dst), "l"(src) : "memory");
}
__device__ __forceinline__ void cp_commit() {
    asm volatile("cp.async.commit_group;" ::: "memory");
}
template <int N>
__device__ __forceinline__ void cp_wait() {
    asm volatile("cp.async.wait_group %0;" :: "n"(N) : "memory");
}

__device__ __forceinline__ void ldm4(uint32_t* r, uint32_t addr) {
    asm volatile("ldmatrix.sync.aligned.m8n8.x4.shared.b16 {%0,%1,%2,%3}, [%4];"
                 : "=r"(r[0]), "=r"(r[1]), "=r"(r[2]), "=r"(r[3]) : "r"(addr));
}

__device__ __forceinline__ void mma_f16(float* d, const uint32_t* a, const uint32_t* b) {
    asm volatile(
        "mma.sync.aligned.m16n8k16.row.col.f32.f16.f16.f32 "
        "{%0,%1,%2,%3}, {%4,%5,%6,%7}, {%8,%9}, {%0,%1,%2,%3};"
        : "+f"(d[0]), "+f"(d[1]), "+f"(d[2]), "+f"(d[3])
        : "r"(a[0]), "r"(a[1]), "r"(a[2]), "r"(a[3]), "r"(b[0]), "r"(b[1]));
}

// ---------------------------------------------------------------------------
// Plain fp16 GEMM, fully K-resident: 4 buffers (BK=64 each), ONE sync,
// then barrier-free 128-MMA mainloop.  C[M,N] = A[M,256] @ B[N,256]^T.
// Block tile 64x128, warp tile 32x32 (2m x 4n), 256 threads, 2 CTAs/SM.
// smem: 4 x (A 9216 + B 18432) = 110592 B.
// EPI 0: fp16 out    EPI 1: gelu -> fp16 out    EPI 2: fp32 +res -> C
// ---------------------------------------------------------------------------
#define SSTR 72                      // smem row stride in fp16 elems (144B)
#define A_TILEB (64 * SSTR * 2)      // 9216
#define B_TILEB (128 * SSTR * 2)     // 18432
#define SETB (A_TILEB + B_TILEB)     // 27648
#define SMEM_TOTAL (4 * SETB)        // 110592

template <int EPI>
__global__ __launch_bounds__(256, 2) void tc_gemm(
    const __half* __restrict__ Ah, const __half* __restrict__ Bh,
    const float* __restrict__ bias, const float* __restrict__ res,
    float* __restrict__ C, __half* __restrict__ Ch, int ldc)
{
    extern __shared__ __align__(128) unsigned char smraw[];

    const int t    = threadIdx.x;
    const int lane = t & 31;
    const int wid  = t >> 5;
    const int wm   = wid & 1;
    const int wn   = wid >> 1;
    const int m0   = blockIdx.x * 64;
    const int n0   = blockIdx.y * 128;

    const uint32_t sb = smem_u32(smraw);
    const int lrow8 = t >> 3;         // 0..31
    const int lcol8 = (t & 7) * 8;    // elem offset in 64-col chunk

    float acc[2][4][4];
#pragma unroll
    for (int i = 0; i < 2; i++)
#pragma unroll
        for (int j = 0; j < 4; j++)
#pragma unroll
            for (int q = 0; q < 4; q++) acc[i][j][q] = 0.0f;

    // Issue all 4 k-chunks up front (one commit group each)
#pragma unroll
    for (int s = 0; s < 4; s++) {
        const int k0 = s * 64;
        const uint32_t base = sb + (uint32_t)s * SETB;
        const uint32_t roff = (uint32_t)(lrow8 * SSTR + lcol8) * 2;
        cp_async16(base + roff, Ah + (size_t)(m0 + lrow8) * CDIM + k0 + lcol8);
        cp_async16(base + roff + 32 * SSTR * 2,
                   Ah + (size_t)(m0 + lrow8 + 32) * CDIM + k0 + lcol8);
        const uint32_t bbase = base + A_TILEB;
#pragma unroll
        for (int g = 0; g < 4; g++) {
            cp_async16(bbase + roff + g * 32 * SSTR * 2,
                       Bh + (size_t)(n0 + lrow8 + g * 32) * CDIM + k0 + lcol8);
        }
        cp_commit();
    }

    const int rsel  = lane & 15;
    const int khalf = (lane >> 4) * 8;
    const uint32_t aoff = (uint32_t)((wm * 32 + rsel) * SSTR + khalf) * 2;
    const uint32_t boff = (uint32_t)((wn * 32 + rsel) * SSTR + khalf) * 2;

    cp_wait<0>();
    __syncthreads();

    // Barrier-free mainloop over all 4 chunks x 4 k-steps
#pragma unroll
    for (int s = 0; s < 4; s++) {
        const uint32_t base = sb + (uint32_t)s * SETB;
        const uint32_t ah = base + aoff;
        const uint32_t bh = base + A_TILEB + boff;
#pragma unroll
        for (int ks = 0; ks < 4; ks++) {
            const uint32_t koff = (uint32_t)(ks * 16) * 2;

            uint32_t a[2][4];
#pragma unroll
            for (int im = 0; im < 2; im++)
                ldm4(a[im], ah + (uint32_t)(im * 16 * SSTR) * 2 + koff);

            uint32_t bf[4][2];
#pragma unroll
            for (int ib = 0; ib < 2; ib++) {
                uint32_t q[4];
                ldm4(q, bh + (uint32_t)(ib * 16 * SSTR) * 2 + koff);
                bf[ib * 2 + 0][0] = q[0]; bf[ib * 2 + 0][1] = q[2];
                bf[ib * 2 + 1][0] = q[1]; bf[ib * 2 + 1][1] = q[3];
            }

#pragma unroll
            for (int im = 0; im < 2; im++)
#pragma unroll
                for (int jn = 0; jn < 4; jn++) mma_f16(acc[im][jn], a[im], bf[jn]);
        }
    }

    // Epilogue
    const int cbase = n0 + wn * 32 + (lane & 3) * 2;
#pragma unroll
    for (int im = 0; im < 2; im++) {
        const int rbase = m0 + wm * 32 + im * 16 + (lane >> 2);
#pragma unroll
        for (int half = 0; half < 2; half++) {
            const int row = rbase + half * 8;
#pragma unroll
            for (int jn = 0; jn < 4; jn++) {
                const int col = cbase + jn * 8;
                float v0 = acc[im][jn][half * 2 + 0] + bias[col];
                float v1 = acc[im][jn][half * 2 + 1] + bias[col + 1];
                if (EPI == 0) {
                    __half2 p;
                    p.x = __float2half_rn(v0);
                    p.y = __float2half_rn(v1);
                    *(__half2*)(Ch + (size_t)row * ldc + col) = p;
                } else if (EPI == 1) {
                    v0 = 0.5f * v0 * (1.0f + erff(v0 * 0.7071067811865476f));
                    v1 = 0.5f * v1 * (1.0f + erff(v1 * 0.7071067811865476f));
                    __half2 p;
                    p.x = __float2half_rn(v0);
                    p.y = __float2half_rn(v1);
                    *(__half2*)(Ch + (size_t)row * ldc + col) = p;
                } else {
                    float2 rv = *(const float2*)(res + (size_t)row * ldc + col);
                    *(float2*)(C + (size_t)row * ldc + col) = make_float2(v0 + rv.x, v1 + rv.y);
                }
            }
        }
    }
}

// ---------------------------------------------------------------------------
// x -> fp16 convert
// ---------------------------------------------------------------------------
__global__ __launch_bounds__(256) void xcvt_kernel(
    const float* __restrict__ in, __half* __restrict__ hi, int n)
{
    int i = (blockIdx.x * 256 + threadIdx.x) * 4;
    if (i >= n) return;
    float4 v = *(const float4*)(in + i);
    __half2 p0, p1;
    p0.x = __float2half_rn(v.x); p0.y = __float2half_rn(v.y);
    p1.x = __float2half_rn(v.z); p1.y = __float2half_rn(v.w);
    *(__half2*)(hi + i)     = p0;
    *(__half2*)(hi + i + 2) = p1;
}

// Weight transpose + fp16 convert: w [K,N] -> [N,K]
__global__ __launch_bounds__(256) void wcvt_kernel(
    const float* __restrict__ w, __half* __restrict__ hi, int K, int N)
{
    int idx = blockIdx.x * 256 + threadIdx.x;
    if (idx >= K * N) return;
    int nn = idx / K;
    int kk = idx - nn * K;
    hi[idx] = __float2half_rn(w[(size_t)kk * N + nn]);
}

// Merged w1+w2 convert (both 256x256)
__global__ __launch_bounds__(256) void wcvt2_kernel(
    const float* __restrict__ w1, const float* __restrict__ w2,
    __half* __restrict__ h1, __half* __restrict__ h2)
{
    int idx = blockIdx.x * 256 + threadIdx.x;
    const int tot = CDIM * CDIM;
    const float* w = (idx < tot) ? w1 : w2;
    __half* hh     = (idx < tot) ? h1 : h2;
    int i = (idx < tot) ? idx : idx - tot;
    if (idx >= 2 * tot) return;
    int nn = i / CDIM;
    int kk = i - nn * CDIM;
    hh[i] = __float2half_rn(w[(size_t)kk * CDIM + nn]);
}

// ---------------------------------------------------------------------------
// kv_partial: LN packed f16 reductions + tensor-core outer product (fp16)
// ---------------------------------------------------------------------------
#define KV_SMEM 65536

__global__ __launch_bounds__(256) void kv_partial_kernel(
    const float* __restrict__ kg, const float* __restrict__ kb,
    const float* __restrict__ vg, const float* __restrict__ vb)
{
    extern __shared__ __align__(128) unsigned char smraw[];

    const int chunk = blockIdx.x;
    const int bh    = blockIdx.y;
    const int b = bh >> 3, h = bh & 7;
    const int t = threadIdx.x, w = t >> 5, lane = t & 31;

    const uint32_t sb    = smem_u32(smraw);
    const uint32_t kbase = sb + (uint32_t)w * 8192;
    const uint32_t vbase = kbase + 4096;
    const uint32_t dsw   = (uint32_t)(lane & 7) << 4;

    const float gkl = kg[lane], bkl = kb[lane];
    const float gvl = vg[lane], bvl = vb[lane];

    const int row0 = chunk * 512 + w * 64;

    uint32_t kpack[4], vpack[4];

    for (int r = 0; r < 64; r += 2) {
        const __half* r1 = g_qkvh + (size_t)(b * HW + row0 + r) * QKVN + h * 96;
        const __half* r2 = r1 + QKVN;
        float kx1 = __half2float(r1[32 + lane]);
        float vx1 = __half2float(r1[64 + lane]);
        float kx2 = __half2float(r2[32 + lane]);
        float vx2 = __half2float(r2[64 + lane]);

        __half2 s1 = __floats2half2_rn(kx1, vx1);
        __half2 s2 = __floats2half2_rn(kx2, vx2);
#pragma unroll
        for (int off = 16; off > 0; off >>= 1) {
            uint32_t u1 = __shfl_xor_sync(0xffffffffu, *(uint32_t*)&s1, off);
            uint32_t u2 = __shfl_xor_sync(0xffffffffu, *(uint32_t*)&s2, off);
            s1 = __hadd2(s1, *(__half2*)&u1);
            s2 = __hadd2(s2, *(__half2*)&u2);
        }
        float2 f1 = __half22float2(s1);
        float2 f2 = __half22float2(s2);
        float dk1 = kx1 - f1.x * (1.0f / 32.0f);
        float dv1 = vx1 - f1.y * (1.0f / 32.0f);
        float dk2 = kx2 - f2.x * (1.0f / 32.0f);
        float dv2 = vx2 - f2.y * (1.0f / 32.0f);

        __half2 q1 = __floats2half2_rn(dk1 * dk1, dv1 * dv1);
        __half2 q2 = __floats2half2_rn(dk2 * dk2, dv2 * dv2);
#pragma unroll
        for (int off = 16; off > 0; off >>= 1) {
            uint32_t u1 = __shfl_xor_sync(0xffffffffu, *(uint32_t*)&q1, off);
            uint32_t u2 = __shfl_xor_sync(0xffffffffu, *(uint32_t*)&q2, off);
            q1 = __hadd2(q1, *(__half2*)&u1);
            q2 = __hadd2(q2, *(__half2*)&u2);
        }
        float2 g1 = __half22float2(q1);
        float2 g2 = __half22float2(q2);

        float kn1 = dk1 * rsqrtf(g1.x * (1.0f / 32.0f) + 1e-5f) * gkl + bkl;
        float vn1 = dv1 * rsqrtf(g1.y * (1.0f / 32.0f) + 1e-5f) * gvl + bvl;
        float kn2 = dk2 * rsqrtf(g2.x * (1.0f / 32.0f) + 1e-5f) * gkl + bkl;
        float vn2 = dv2 * rsqrtf(g2.y * (1.0f / 32.0f) + 1e-5f) * gvl + bvl;

        const int j = (r & 7) >> 1;
        __half2 kp = __floats2half2_rn(kn1, kn2);
        __half2 vp = __floats2half2_rn(vn1, vn2);
        kpack[j] = *(uint32_t*)&kp;
        vpack[j] = *(uint32_t*)&vp;

        if ((r & 7) == 6) {
            const uint32_t caddr = (uint32_t)((r - 6) * 2) ^ dsw;
            const uint32_t rowb  = (uint32_t)lane * 128;
            asm volatile("st.shared.v4.b32 [%0], {%1,%2,%3,%4};"
                         :: "r"(kbase + rowb + caddr),
                            "r"(kpack[0]), "r"(kpack[1]), "r"(kpack[2]), "r"(kpack[3])
                         : "memory");
            asm volatile("st.shared.v4.b32 [%0], {%1,%2,%3,%4};"
                         :: "r"(vbase + rowb + caddr),
                            "r"(vpack[0]), "r"(vpack[1]), "r"(vpack[2]), "r"(vpack[3])
                         : "memory");
        }
    }
    __syncwarp();

    float acc[2][4][4];
#pragma unroll
    for (int i = 0; i < 2; i++)
#pragma unroll
        for (int j = 0; j < 4; j++)
#pragma unroll
            for (int q = 0; q < 4; q++) acc[i][j][q] = 0.0f;

    const int rsel  = lane & 15;
    const uint32_t lsw  = (uint32_t)(rsel & 7) << 4;
    const uint32_t kh16 = (uint32_t)(lane >> 4) * 16;

#pragma unroll
    for (int ks = 0; ks < 4; ks++) {
        const uint32_t cb = (uint32_t)(ks * 32);

        uint32_t a[2][4];
#pragma unroll
        for (int im = 0; im < 2; im++) {
            const uint32_t rowb = (uint32_t)(im * 16 + rsel) * 128;
            ldm4(a[im], kbase + rowb + ((cb + kh16) ^ lsw));
        }

        uint32_t bf[4][2];
#pragma unroll
        for (int ib = 0; ib < 2; ib++) {
            const uint32_t rowb = (uint32_t)(ib * 16 + rsel) * 128;
            uint32_t q[4];
            ldm4(q, vbase + rowb + ((cb + kh16) ^ lsw));
            bf[ib * 2 + 0][0] = q[0]; bf[ib * 2 + 0][1] = q[2];
            bf[ib * 2 + 1][0] = q[1]; bf[ib * 2 + 1][1] = q[3];
        }
#pragma unroll
        for (int im = 0; im < 2; im++)
#pragma unroll
            for (int jn = 0; jn < 4; jn++) mma_f16(acc[im][jn], a[im], bf[jn]);
    }

    __syncthreads();
    float* buf = (float*)smraw;
#pragma unroll
    for (int im = 0; im < 2; im++)
#pragma unroll
        for (int half = 0; half < 2; half++) {
            const int row = im * 16 + (lane >> 2) + half * 8;
#pragma unroll
            for (int jn = 0; jn < 4; jn++) {
                const int col = (lane & 3) * 2 + jn * 8;
                buf[(w * 32 + row) * 32 + col]     = acc[im][jn][half * 2 + 0];
                buf[(w * 32 + row) * 32 + col + 1] = acc[im][jn][half * 2 + 1];
            }
        }
    __syncthreads();

    float* outp = g_kvp + ((size_t)bh * KV_CH + chunk) * (HC * HC);
    for (int idx = t; idx < HC * HC; idx += 256) {
        float s = 0.0f;
#pragma unroll
        for (int ww = 0; ww < 8; ww++) s += buf[(ww * 32 + (idx >> 5)) * 32 + (idx & 31)];
        outp[idx] = s * (1.0f / (float)HW);
    }
}

// ---------------------------------------------------------------------------
// attn_out: ret = q @ kv + x -> fp16 g_reth (q fp16)
// ---------------------------------------------------------------------------
__global__ __launch_bounds__(256) void attn_out_kernel(const float* __restrict__ x)
{
    const int chunk = blockIdx.x;
    const int bh    = blockIdx.y;
    const int b = bh >> 3, h = bh & 7;
    const int t = threadIdx.x;

    __shared__ float kv[HC][HC];
    for (int idx = t; idx < HC * HC; idx += 256) {
        float s = 0.0f;
#pragma unroll
        for (int c = 0; c < KV_CH; c++)
            s += g_kvp[((size_t)bh * KV_CH + c) * (HC * HC) + idx];
        kv[idx >> 5][idx & 31] = s;
    }
    __syncthreads();

    const int n = chunk * 256 + t;
    const size_t rowg = (size_t)(b * HW + n);
    const __half* q = g_qkvh + rowg * QKVN + h * 96;

    float qv[32];
#pragma unroll
    for (int i = 0; i < 4; i++) {
        uint4 u = ((const uint4*)q)[i];
        const __half2* pp = (const __half2*)&u;
#pragma unroll
        for (int j = 0; j < 4; j++) {
            float2 f = __half22float2(pp[j]);
            qv[i * 8 + j * 2 + 0] = f.x;
            qv[i * 8 + j * 2 + 1] = f.y;
        }
    }

    float acc[32];
#pragma unroll
    for (int j = 0; j < 32; j++) acc[j] = 0.0f;
#pragma unroll
    for (int i = 0; i < 32; i++) {
        float qi = qv[i];
#pragma unroll
        for (int j = 0; j < 32; j++) acc[j] += qi * kv[i][j];
    }

    const float* xr = x + rowg * CDIM + h * HC;
    __half* hr = g_reth + rowg * CDIM + h * HC;
#pragma unroll
    for (int j = 0; j < 32; j += 4) {
        float4 xv = *(const float4*)(xr + j);
        __half2 p0, p1;
        p0.x = __float2half_rn(acc[j]     + xv.x);
        p0.y = __float2half_rn(acc[j + 1] + xv.y);
        p1.x = __float2half_rn(acc[j + 2] + xv.z);
        p1.y = __float2half_rn(acc[j + 3] + xv.w);
        *(__half2*)(hr + j)     = p0;
        *(__half2*)(hr + j + 2) = p1;
    }
}

// ---------------------------------------------------------------------------
// Launch  (tc_gemm<0> at launch #4 for profiling)
// ---------------------------------------------------------------------------
extern "C" void kernel_launch(void* const* d_in, const int* in_sizes, int n_in,
                              void* d_out, int out_size)
{
    const float* x     = (const float*)d_in[0];
    const float* w_qkv = (const float*)d_in[1];
    const float* b_qkv = (const float*)d_in[2];
    const float* kln_g = (const float*)d_in[3];
    const float* kln_b = (const float*)d_in[4];
    const float* vln_g = (const float*)d_in[5];
    const float* vln_b = (const float*)d_in[6];
    const float* w1    = (const float*)d_in[7];
    const float* b1    = (const float*)d_in[8];
    const float* w2    = (const float*)d_in[9];
    const float* b2    = (const float*)d_in[10];
    float* out = (float*)d_out;

    void *p_qkvh, *p_xh, *p_reth, *p_hidh, *p_wqh, *p_w1h, *p_w2h;
    cudaGetSymbolAddress(&p_qkvh, g_qkvh);
    cudaGetSymbolAddress(&p_xh, g_xh);
    cudaGetSymbolAddress(&p_reth, g_reth);
    cudaGetSymbolAddress(&p_hidh, g_hidh);
    cudaGetSymbolAddress(&p_wqh, g_wqh);
    cudaGetSymbolAddress(&p_w1h, g_w1h);
    cudaGetSymbolAddress(&p_w2h, g_w2h);

    static int s_attr_done = 0;
    if (!s_attr_done) {
        cudaFuncSetAttribute(tc_gemm<0>, cudaFuncAttributeMaxDynamicSharedMemorySize, SMEM_TOTAL);
        cudaFuncSetAttribute(tc_gemm<1>, cudaFuncAttributeMaxDynamicSharedMemorySize, SMEM_TOTAL);
        cudaFuncSetAttribute(tc_gemm<2>, cudaFuncAttributeMaxDynamicSharedMemorySize, SMEM_TOTAL);
        cudaFuncSetAttribute(kv_partial_kernel, cudaFuncAttributeMaxDynamicSharedMemorySize, KV_SMEM);
        s_attr_done = 1;
    }

    const int nx = MROWS * CDIM;

    // 1: x -> fp16, 2: wqkv cvt, 3: w1+w2 cvt (merged)
    xcvt_kernel<<<(nx / 4 + 255) / 256, 256>>>(x, (__half*)p_xh, nx);
    wcvt_kernel<<<(CDIM * QKVN + 255) / 256, 256>>>(w_qkv, (__half*)p_wqh, CDIM, QKVN);
    wcvt2_kernel<<<(2 * CDIM * CDIM + 255) / 256, 256>>>(
        w1, w2, (__half*)p_w1h, (__half*)p_w2h);

    // 4: qkv GEMM (PROFILED): all outputs fp16 -> g_qkvh
    tc_gemm<0><<<dim3(MROWS / 64, QKVN / 128), 256, SMEM_TOTAL>>>(
        (const __half*)p_xh, (const __half*)p_wqh,
        b_qkv, nullptr, nullptr, (__half*)p_qkvh, QKVN);

    // 5: kv_partial, 6: attn_out
    kv_partial_kernel<<<dim3(KV_CH, BDIM * NHEAD), 256, KV_SMEM>>>(kln_g, kln_b, vln_g, vln_b);
    attn_out_kernel<<<dim3(16, BDIM * NHEAD), 256>>>(x);

    // 7: MLP1 -> fp16 hid
    tc_gemm<1><<<dim3(MROWS / 64, CDIM / 128), 256, SMEM_TOTAL>>>(
        (const __half*)p_reth, (const __half*)p_w1h,
        b1, nullptr, nullptr, (__half*)p_hidh, CDIM);

    // 8: MLP2 -> out (fp32 + residual)
    tc_gemm<2><<<dim3(MROWS / 64, CDIM / 128), 256, SMEM_TOTAL>>>(
        (const __half*)p_hidh, (const __half*)p_w2h,
        b2, x, out, nullptr, CDIM);
}